// round 1
// baseline (speedup 1.0000x reference)
#include <cuda_runtime.h>
#include <math.h>

// ---------------------------------------------------------------------------
// Intermediate activation buffers (device globals — no allocation allowed).
// Layouts all [B, C, T, D, H, W] contiguous.
// ---------------------------------------------------------------------------
__device__ float g_a1[38880000];   // 256*3*15^4
__device__ float g_a2[15925248];   // 256*3*12^4
__device__ float g_a3[6718464];    // 256*4*9^4
__device__ float g_a4[1658880];    // 256*5*6^4
__device__ float g_a5[327680];     // 256*5*4^4  (== flattened [256,1280])

// ---------------------------------------------------------------------------
// Direct 4D valid convolution + bias + ReLU.
//   in : [B, CIN, S, S, S, S]
//   w  : [COUT, CIN, K, K, K, K]
//   out: [B, COUT, O, O, O, O],  O = S-K+1
// Block = (b, t-chunk of TLOC output t positions). Thread owns
// (t_local, d_out, h_out) and computes the full W row for all COUT.
// Input staged one t-slice at a time in SMEM; weights staged once.
// ---------------------------------------------------------------------------
template<int CIN, int COUT, int K, int S, int TLOC, int NTHR>
__global__ void __launch_bounds__(NTHR)
conv_relu(const float* __restrict__ in, float* __restrict__ out,
          const float* __restrict__ w, const float* __restrict__ bias)
{
    constexpr int O      = S - K + 1;       // output extent per dim (incl. T)
    constexpr int TO     = O;
    constexpr int TCH    = TO / TLOC;       // t-chunks per batch
    constexpr int NSTAGE = TLOC + K - 1;    // input t-slices needed per chunk
    constexpr int S2 = S * S;
    constexpr int S3 = S2 * S;
    constexpr int S4 = S3 * S;
    constexpr int O2 = O * O;
    constexpr int O3 = O2 * O;
    constexpr int KW4 = K * K * K * K;
    constexpr int NW  = COUT * CIN * KW4;
    constexpr int NACT = TLOC * O2;

    __shared__ float s_slice[S3];
    __shared__ float s_w[NW];

    const int bt     = blockIdx.x;
    const int tchunk = bt % TCH;
    const int b      = bt / TCH;
    const int t0     = tchunk * TLOC;
    const int tid    = threadIdx.x;

    // Stage all weights for this layer once.
    for (int i = tid; i < NW; i += NTHR) s_w[i] = w[i];

    const int tl  = tid / O2;
    const int rem = tid - tl * O2;
    const int dd  = rem / O;
    const int hh  = rem - dd * O;
    const bool act = (tid < NACT);

    float acc[COUT][O];
    #pragma unroll
    for (int c = 0; c < COUT; c++)
        #pragma unroll
        for (int r = 0; r < O; r++) acc[c][r] = 0.0f;

    #pragma unroll 1
    for (int ci = 0; ci < CIN; ci++) {
        #pragma unroll 1
        for (int s = 0; s < NSTAGE; s++) {
            __syncthreads();
            const float* src = in + (size_t)(b * CIN + ci) * S4
                                  + (size_t)(t0 + s) * S3;
            for (int i = tid; i < S3; i += NTHR) s_slice[i] = src[i];
            __syncthreads();

            const int kt = s - tl;              // which kernel-t tap this slice is
            if (act && kt >= 0 && kt < K) {
                const float* wb = s_w + (ci * K + kt) * (K * K * K);
                #pragma unroll 1
                for (int kd = 0; kd < K; kd++) {
                    #pragma unroll
                    for (int kh = 0; kh < K; kh++) {
                        const float* rp = s_slice + (dd + kd) * S2 + (hh + kh) * S;
                        float row[S];
                        #pragma unroll
                        for (int x = 0; x < S; x++) row[x] = rp[x];

                        float wr[COUT][K];
                        #pragma unroll
                        for (int co = 0; co < COUT; co++)
                            #pragma unroll
                            for (int kw = 0; kw < K; kw++)
                                wr[co][kw] = wb[co * CIN * KW4 + (kd * K + kh) * K + kw];

                        #pragma unroll
                        for (int kw = 0; kw < K; kw++)
                            #pragma unroll
                            for (int r = 0; r < O; r++)
                                #pragma unroll
                                for (int co = 0; co < COUT; co++)
                                    acc[co][r] = fmaf(wr[co][kw], row[r + kw], acc[co][r]);
                    }
                }
            }
        }
    }

    if (act) {
        const int t = t0 + tl;
        #pragma unroll
        for (int co = 0; co < COUT; co++) {
            const float bv = bias[co];
            float* op = out + (size_t)(b * COUT + co) * (TO * O3)
                            + (size_t)t * O3 + (dd * O + hh) * O;
            #pragma unroll
            for (int r = 0; r < O; r++)
                op[r] = fmaxf(acc[co][r] + bv, 0.0f);
        }
    }
}

// ---------------------------------------------------------------------------
// Fused FC1(1280->33) + ReLU + FC2(33->1) + sigmoid. One block per batch row.
// ---------------------------------------------------------------------------
__global__ void __launch_bounds__(64)
fc_head(const float* __restrict__ h,
        const float* __restrict__ fc1w, const float* __restrict__ fc1b,
        const float* __restrict__ fc2w, const float* __restrict__ fc2b,
        float* __restrict__ out)
{
    __shared__ float sh[1280];
    __shared__ float so[33];
    const int b = blockIdx.x;

    for (int i = threadIdx.x; i < 1280; i += 64) sh[i] = h[(size_t)b * 1280 + i];
    __syncthreads();

    const int co = threadIdx.x;
    if (co < 33) {
        float a = 0.0f;
        const float* wr = fc1w + co * 1280;
        #pragma unroll 4
        for (int k = 0; k < 1280; k++) a = fmaf(sh[k], __ldg(&wr[k]), a);
        so[co] = fmaxf(a + fc1b[co], 0.0f);
    }
    __syncthreads();

    if (threadIdx.x == 0) {
        float z = fc2b[0];
        #pragma unroll
        for (int j = 0; j < 33; j++) z = fmaf(so[j], __ldg(&fc2w[j]), z);
        out[b] = 1.0f / (1.0f + expf(-z));
    }
}

// ---------------------------------------------------------------------------
// Inputs (metadata order):
// 0:x 1:w1 2:b1 3:w2 4:b2 5:w3 6:b3 7:w4 8:b4 9:w5 10:b5
// 11:fc1_w 12:fc1_b 13:fc2_w 14:fc2_b    -> out: [B,1] float32
// ---------------------------------------------------------------------------
extern "C" void kernel_launch(void* const* d_in, const int* in_sizes, int n_in,
                              void* d_out, int out_size)
{
    const float* x    = (const float*)d_in[0];
    const float* w1   = (const float*)d_in[1];
    const float* b1   = (const float*)d_in[2];
    const float* w2   = (const float*)d_in[3];
    const float* b2   = (const float*)d_in[4];
    const float* w3   = (const float*)d_in[5];
    const float* b3   = (const float*)d_in[6];
    const float* w4   = (const float*)d_in[7];
    const float* b4   = (const float*)d_in[8];
    const float* w5   = (const float*)d_in[9];
    const float* b5   = (const float*)d_in[10];
    const float* f1w  = (const float*)d_in[11];
    const float* f1b  = (const float*)d_in[12];
    const float* f2w  = (const float*)d_in[13];
    const float* f2b  = (const float*)d_in[14];

    const int B = in_sizes[0] / (18 * 18 * 18 * 18);

    float *a1, *a2, *a3, *a4, *a5;
    cudaGetSymbolAddress((void**)&a1, g_a1);
    cudaGetSymbolAddress((void**)&a2, g_a2);
    cudaGetSymbolAddress((void**)&a3, g_a3);
    cudaGetSymbolAddress((void**)&a4, g_a4);
    cudaGetSymbolAddress((void**)&a5, g_a5);

    // L1: 18^4 -> 15^4, Cin=1, Cout=3, k=4
    conv_relu<1, 3, 4, 18, 1, 256><<<B * 15, 256>>>(x,  a1, w1, b1);
    // L2: 15^4 -> 12^4, 3->3, k=4
    conv_relu<3, 3, 4, 15, 1, 256><<<B * 12, 256>>>(a1, a2, w2, b2);
    // L3: 12^4 -> 9^4, 3->4, k=4   (TLOC=3 -> 243 active threads)
    conv_relu<3, 4, 4, 12, 3, 256><<<B * 3,  256>>>(a2, a3, w3, b3);
    // L4: 9^4 -> 6^4, 4->5, k=4    (TLOC=3 -> 108 active threads)
    conv_relu<4, 5, 4, 9,  3, 128><<<B * 2,  128>>>(a3, a4, w4, b4);
    // L5: 6^4 -> 4^4, 5->5, k=3    (TLOC=4 -> 64 active threads)
    conv_relu<5, 5, 3, 6,  4, 128><<<B * 1,  128>>>(a4, a5, w5, b5);

    // FC head: [B,1280] -> [B,33] -> [B,1] sigmoid
    fc_head<<<B, 64>>>(a5, f1w, f1b, f2w, f2b, (float*)d_out);
}